// round 14
// baseline (speedup 1.0000x reference)
#include <cuda_runtime.h>
#include <math.h>

// ZoneOutLSTM: T=512, B=32, D=512, H=1024, L=2, p_zoneout=0.1
// Persistent kernel: 128 CTAs x 128 threads, software-pipelined so there is
// exactly ONE grid barrier per timestep. Each CTA owns 8 hidden units
// (= 32 gate rows: i/f/g/o x 8) for both layers. GEMMs use k-pair-packed
// fp32x2 FFMA with double-buffered cp.async.cg staging.

#define TT 512
#define BB 32
#define DD 512
#define HH 1024
#define NCTA 128
#define NTHR 128
#define KC 64           // k-chunk size
#define SRS 68          // padded smem row stride (floats); 68*4B = 17*16B

// ---------------- device globals (scratch; allocations forbidden) -----------
__device__ __align__(16) float g_h_state[2][2][BB * HH]; // [parity][layer][b*H+h] post-zoneout
__device__ __align__(16) float g_h0new[2][BB * HH];      // [parity][b*H+h] layer0 h pre-zoneout
__device__ unsigned g_bar;                               // grid barrier counter

// ---------------- helpers ---------------------------------------------------
__device__ __forceinline__ void ffma2(unsigned long long& d,
                                      unsigned long long a,
                                      unsigned long long b) {
  // packed: d.lo += a.lo*b.lo ; d.hi += a.hi*b.hi
  asm("fma.rn.f32x2 %0, %1, %2, %0;" : "+l"(d) : "l"(a), "l"(b));
}

__device__ __forceinline__ void cp_async16(void* sdst, const void* gsrc) {
  unsigned s = (unsigned)__cvta_generic_to_shared(sdst);
  asm volatile("cp.async.cg.shared.global [%0], [%1], 16;" ::"r"(s), "l"(gsrc));
}
__device__ __forceinline__ void cp_commit() {
  asm volatile("cp.async.commit_group;");
}
template <int N>
__device__ __forceinline__ void cp_wait() {
  asm volatile("cp.async.wait_group %0;" ::"n"(N));
}

__device__ __forceinline__ float pairsum(unsigned long long a) {
  return __uint_as_float((unsigned)a) + __uint_as_float((unsigned)(a >> 32));
}

__device__ __forceinline__ float sigmoidf_(float x) {
  return 1.0f / (1.0f + expf(-x));
}

// Release/acquire grid barrier; target grows monotonically within a launch.
__device__ __forceinline__ void grid_sync(unsigned target) {
  __syncthreads();
  if (threadIdx.x == 0) {
    __threadfence();
    atomicAdd(&g_bar, 1u);
    volatile unsigned* p = &g_bar;
    while (*p < target) __nanosleep(64);
    __threadfence();
  }
  __syncthreads();
}

// ------------- stage one 64-k chunk: W (32 gate rows) + rhs (32 batch) ------
__device__ __forceinline__ void stage_chunk(float (*sWc)[SRS], float (*sRc)[SRS],
                                            const float* __restrict__ W, int ldw,
                                            int u0,
                                            const float* __restrict__ rhs, int ldr,
                                            int k0, int tid) {
#pragma unroll
  for (int i = 0; i < 4; i++) {
    int fidx = tid + NTHR * i;               // 0..511
    int row = fidx >> 4;                     // 0..31 local gate row
    int c4 = (fidx & 15) << 2;               // float offset in chunk
    int grow = ((row >> 3) << 10) + u0 + (row & 7);  // gate*H + unit
    cp_async16(&sWc[row][c4], W + (size_t)grow * ldw + k0 + c4);
  }
#pragma unroll
  for (int i = 0; i < 4; i++) {
    int fidx = tid + NTHR * i;
    int row = fidx >> 4;                     // batch index
    int c4 = (fidx & 15) << 2;
    cp_async16(&sRc[row][c4], rhs + (size_t)row * ldr + k0 + c4);
  }
  cp_commit();
}

// ---- sub-GEMM: acc[2][4] += W[32 x K] * rhs[K x 32], k-pair accumulators ---
__device__ __forceinline__ void sub_gemm(unsigned long long acc[2][4],
                                         const float* __restrict__ W, int ldw,
                                         int u0,
                                         const float* __restrict__ rhs, int ldr,
                                         int K, int tid, int r0, int r1, int bi,
                                         float (*sW)[32][SRS],
                                         float (*sR)[32][SRS]) {
  stage_chunk(sW[0], sR[0], W, ldw, u0, rhs, ldr, 0, tid);
  const int nc = K >> 6;
  int buf = 0;
  for (int ci = 0; ci < nc; ci++) {
    if (ci + 1 < nc) {
      stage_chunk(sW[buf ^ 1], sR[buf ^ 1], W, ldw, u0, rhs, ldr, (ci + 1) << 6, tid);
      cp_wait<1>();
    } else {
      cp_wait<0>();
    }
    __syncthreads();
#pragma unroll
    for (int kk = 0; kk < KC; kk += 4) {
      ulonglong2 w0 = *(const ulonglong2*)&sW[buf][r0][kk];
      ulonglong2 w1 = *(const ulonglong2*)&sW[buf][r1][kk];
#pragma unroll
      for (int j = 0; j < 4; j++) {
        ulonglong2 xv = *(const ulonglong2*)&sR[buf][bi + 8 * j][kk];
        ffma2(acc[0][j], w0.x, xv.x);
        ffma2(acc[0][j], w0.y, xv.y);
        ffma2(acc[1][j], w1.x, xv.x);
        ffma2(acc[1][j], w1.y, xv.y);
      }
    }
    __syncthreads();
    buf ^= 1;
  }
}

// ------------- LSTM cell + zoneout for one (unit, batch) --------------------
__device__ __forceinline__ void cell_update(const float sG[32][33],
                                            const float* sB, int jj, int b,
                                            float uhv, float ucv, float& h_reg,
                                            float& c_reg, float& h_new_out) {
  float gi = sG[jj][b]      + sB[jj];
  float gf = sG[8 + jj][b]  + sB[8 + jj];
  float gg = sG[16 + jj][b] + sB[16 + jj];
  float go = sG[24 + jj][b] + sB[24 + jj];
  float iv = sigmoidf_(gi);
  float fv = sigmoidf_(gf);
  float gv = tanhf(gg);
  float ov = sigmoidf_(go);
  float c_new = fv * c_reg + iv * gv;
  float h_new = ov * tanhf(c_new);
  h_new_out = h_new;
  c_reg = (ucv < 0.9f) ? c_new : c_reg;  // zoneout keep-mask
  h_reg = (uhv < 0.9f) ? h_new : h_reg;
}

// ---------------- init: reset barrier, zero parity-1 initial state ----------
__global__ void lstm_init_kernel() {
  unsigned i = blockIdx.x * blockDim.x + threadIdx.x;
  if (i == 0) g_bar = 0u;
  if (i < BB * HH) {
    g_h_state[1][0][i] = 0.0f;
    g_h_state[1][1][i] = 0.0f;
  }
}

// ---------------- main persistent kernel ------------------------------------
__global__ void __launch_bounds__(NTHR, 1)
lstm_main_kernel(const float* __restrict__ x,
                 const float* __restrict__ Wih0, const float* __restrict__ Whh0,
                 const float* __restrict__ bih0, const float* __restrict__ bhh0,
                 const float* __restrict__ Wih1, const float* __restrict__ Whh1,
                 const float* __restrict__ bih1, const float* __restrict__ bhh1,
                 const float* __restrict__ u_h, const float* __restrict__ u_c,
                 float* __restrict__ out) {
  __shared__ __align__(16) float sW[2][32][SRS];
  __shared__ __align__(16) float sR[2][32][SRS];
  __shared__ float sG[32][33];
  __shared__ float sB[2][32];

  const int tid = threadIdx.x;
  const int u0 = blockIdx.x * 8;          // first hidden unit owned by this CTA
  const int r0 = (tid >> 3) * 2;          // gemm thread tile: rows r0, r0+1
  const int r1 = r0 + 1;
  const int bi = tid & 7;                 // batches bi, bi+8, bi+16, bi+24
  const int jj0 = tid >> 5;               // cell mapping: units jj0, jj0+4
  const int cb = tid & 31;                // cell batch

  if (tid < 32) {
    int grow = (tid >> 3) * HH + u0 + (tid & 7);
    sB[0][tid] = bih0[grow] + bhh0[grow];
    sB[1][tid] = bih1[grow] + bhh1[grow];
  }
  __syncthreads();

  float h_reg[2][2] = {{0.f, 0.f}, {0.f, 0.f}};  // [layer][q]
  float c_reg[2][2] = {{0.f, 0.f}, {0.f, 0.f}};
  unsigned target = 0;

  for (int phase = 0; phase <= TT; phase++) {
    // ======== Layer 1 for step t = phase-1 ========
    if (phase >= 1) {
      const int t = phase - 1;
      unsigned long long acc[2][4] = {};
      sub_gemm(acc, Wih1, HH, u0, g_h0new[t & 1], HH, HH, tid, r0, r1, bi, sW, sR);
      sub_gemm(acc, Whh1, HH, u0, g_h_state[(t + 1) & 1][1], HH, HH, tid, r0, r1,
               bi, sW, sR);
#pragma unroll
      for (int j = 0; j < 4; j++) {
        sG[r0][bi + 8 * j] = pairsum(acc[0][j]);
        sG[r1][bi + 8 * j] = pairsum(acc[1][j]);
      }
      __syncthreads();
#pragma unroll
      for (int q = 0; q < 2; q++) {
        int jj = jj0 + 4 * q;
        int hg = u0 + jj;
        size_t uoff = (((size_t)t * 2 + 1) * BB + cb) * HH + hg;
        float hn;
        cell_update(sG, sB[1], jj, cb, __ldcs(&u_h[uoff]), __ldcs(&u_c[uoff]),
                    h_reg[1][q], c_reg[1][q], hn);
        out[((size_t)t * BB + cb) * HH + hg] = hn;           // pre-zoneout
        g_h_state[t & 1][1][cb * HH + hg] = h_reg[1][q];     // post-zoneout
      }
      __syncthreads();
    }
    // ======== Layer 0 for step t = phase ========
    if (phase <= TT - 1) {
      const int t = phase;
      unsigned long long acc[2][4] = {};
      sub_gemm(acc, Wih0, DD, u0, x + (size_t)t * BB * DD, DD, DD, tid, r0, r1,
               bi, sW, sR);
      sub_gemm(acc, Whh0, HH, u0, g_h_state[(t + 1) & 1][0], HH, HH, tid, r0, r1,
               bi, sW, sR);
#pragma unroll
      for (int j = 0; j < 4; j++) {
        sG[r0][bi + 8 * j] = pairsum(acc[0][j]);
        sG[r1][bi + 8 * j] = pairsum(acc[1][j]);
      }
      __syncthreads();
#pragma unroll
      for (int q = 0; q < 2; q++) {
        int jj = jj0 + 4 * q;
        int hg = u0 + jj;
        size_t uoff = (((size_t)t * 2 + 0) * BB + cb) * HH + hg;
        float hn;
        cell_update(sG, sB[0], jj, cb, __ldcs(&u_h[uoff]), __ldcs(&u_c[uoff]),
                    h_reg[0][q], c_reg[0][q], hn);
        g_h0new[t & 1][cb * HH + hg] = hn;                   // pre-zoneout (L1 input)
        g_h_state[t & 1][0][cb * HH + hg] = h_reg[0][q];     // post-zoneout
      }
      target += NCTA;
      grid_sync(target);   // the ONE barrier per step
    }
  }

  // final carries: h_n (L,B,H) then c_n (L,B,H), after outputs (T,B,H)
  float* hn_out = out + (size_t)TT * BB * HH;
  float* cn_out = hn_out + (size_t)2 * BB * HH;
#pragma unroll
  for (int l = 0; l < 2; l++) {
#pragma unroll
    for (int q = 0; q < 2; q++) {
      int hg = u0 + jj0 + 4 * q;
      hn_out[((size_t)l * BB + cb) * HH + hg] = h_reg[l][q];
      cn_out[((size_t)l * BB + cb) * HH + hg] = c_reg[l][q];
    }
  }
}

extern "C" void kernel_launch(void* const* d_in, const int* in_sizes, int n_in,
                              void* d_out, int out_size) {
  const float* x    = (const float*)d_in[0];
  const float* Wih0 = (const float*)d_in[1];
  const float* Whh0 = (const float*)d_in[2];
  const float* bih0 = (const float*)d_in[3];
  const float* bhh0 = (const float*)d_in[4];
  const float* Wih1 = (const float*)d_in[5];
  const float* Whh1 = (const float*)d_in[6];
  const float* bih1 = (const float*)d_in[7];
  const float* bhh1 = (const float*)d_in[8];
  const float* u_h  = (const float*)d_in[9];
  const float* u_c  = (const float*)d_in[10];
  float* out = (float*)d_out;

  lstm_init_kernel<<<(BB * HH + 255) / 256, 256>>>();
  lstm_main_kernel<<<NCTA, NTHR>>>(x, Wih0, Whh0, bih0, bhh0, Wih1, Whh1, bih1,
                                   bhh1, u_h, u_c, out);
}

// round 15
// speedup vs baseline: 1.1016x; 1.1016x over previous
#include <cuda_runtime.h>
#include <math.h>

// ZoneOutLSTM: T=512, B=32, D=512, H=1024, L=2, p_zoneout=0.1
// Persistent kernel: 128 CTAs x 256 threads. Two 128-thread warp-groups split
// each GEMM's K range by chunk parity (each group = the proven 128-thread
// GEMM structure over half of K, with its own double-buffered smem planes and
// named-barrier syncs), then partials are reduced through shared memory.
// One grid barrier per timestep. CTA owns 8 hidden units (32 gate rows).

#define TT 512
#define BB 32
#define DD 512
#define HH 1024
#define NCTA 128
#define NTHR 256
#define GTHR 128        // threads per warp-group
#define KC 64           // k-chunk size
#define SRS 68          // padded smem row stride (floats)

// dynamic smem layout (floats):
//   sW : [2 groups][2 bufs][32][SRS]  = 8704
//   sR : [2 groups][2 bufs][32][SRS]  = 8704
//   sGp: [2 groups][32][33]           = 2112
//   sB : [2][32]                      = 64
#define SM_W 0
#define SM_R (SM_W + 2 * 2 * 32 * SRS)
#define SM_G (SM_R + 2 * 2 * 32 * SRS)
#define SM_B (SM_G + 2 * 32 * 33)
#define SM_TOT_F (SM_B + 64)
#define SM_TOT_BYTES (SM_TOT_F * 4)

// ---------------- device globals (scratch; allocations forbidden) -----------
__device__ __align__(16) float g_h_state[2][2][BB * HH]; // [parity][layer][b*H+h] post-zoneout
__device__ __align__(16) float g_h0new[2][BB * HH];      // [parity][b*H+h] layer0 h pre-zoneout
__device__ unsigned g_bar;                               // grid barrier counter

// ---------------- helpers ---------------------------------------------------
__device__ __forceinline__ void ffma2(unsigned long long& d,
                                      unsigned long long a,
                                      unsigned long long b) {
  asm("fma.rn.f32x2 %0, %1, %2, %0;" : "+l"(d) : "l"(a), "l"(b));
}

__device__ __forceinline__ void cp_async16(void* sdst, const void* gsrc) {
  unsigned s = (unsigned)__cvta_generic_to_shared(sdst);
  asm volatile("cp.async.cg.shared.global [%0], [%1], 16;" ::"r"(s), "l"(gsrc));
}
__device__ __forceinline__ void cp_commit() {
  asm volatile("cp.async.commit_group;");
}
template <int N>
__device__ __forceinline__ void cp_wait() {
  asm volatile("cp.async.wait_group %0;" ::"n"(N));
}

__device__ __forceinline__ void group_sync(int wg) {
  // named barrier per 128-thread warp-group (ids 1 and 2)
  asm volatile("bar.sync %0, %1;" ::"r"(wg + 1), "r"(GTHR) : "memory");
}

__device__ __forceinline__ float pairsum(unsigned long long a) {
  return __uint_as_float((unsigned)a) + __uint_as_float((unsigned)(a >> 32));
}

__device__ __forceinline__ float sigmoidf_(float x) {
  return 1.0f / (1.0f + expf(-x));
}

// Release/acquire grid barrier; target grows monotonically within a launch.
__device__ __forceinline__ void grid_sync(unsigned target) {
  __syncthreads();
  if (threadIdx.x == 0) {
    __threadfence();
    atomicAdd(&g_bar, 1u);
    volatile unsigned* p = &g_bar;
    while (*p < target) __nanosleep(64);
    __threadfence();
  }
  __syncthreads();
}

// ------------- stage one 64-k chunk: W (32 gate rows) + rhs (32 batch) ------
__device__ __forceinline__ void stage_chunk(float (*sWc)[SRS], float (*sRc)[SRS],
                                            const float* __restrict__ W, int ldw,
                                            int u0,
                                            const float* __restrict__ rhs, int ldr,
                                            int k0, int gtid) {
#pragma unroll
  for (int i = 0; i < 4; i++) {
    int fidx = gtid + GTHR * i;              // 0..511
    int row = fidx >> 4;                     // 0..31 local gate row
    int c4 = (fidx & 15) << 2;               // float offset in chunk
    int grow = ((row >> 3) << 10) + u0 + (row & 7);  // gate*H + unit
    cp_async16(&sWc[row][c4], W + (size_t)grow * ldw + k0 + c4);
  }
#pragma unroll
  for (int i = 0; i < 4; i++) {
    int fidx = gtid + GTHR * i;
    int row = fidx >> 4;                     // batch index
    int c4 = (fidx & 15) << 2;
    cp_async16(&sRc[row][c4], rhs + (size_t)row * ldr + k0 + c4);
  }
  cp_commit();
}

// ---- sub-GEMM (one warp-group, chunks of parity wg):
//      acc[2][4] += W[32 x K_sub] * rhs[K_sub x 32], k-pair accumulators ----
__device__ __forceinline__ void sub_gemm(unsigned long long acc[2][4],
                                         const float* __restrict__ W, int ldw,
                                         int u0,
                                         const float* __restrict__ rhs, int ldr,
                                         int K, int wg, int gtid, int r0, int r1,
                                         int bi,
                                         float (*gW)[32][SRS],
                                         float (*gR)[32][SRS]) {
  const int ncg = (K >> 6) >> 1;             // chunks per group (always >=4)
  // first chunk of this group: ci = wg
  stage_chunk(gW[0], gR[0], W, ldw, u0, rhs, ldr, wg << 6, gtid);
  int buf = 0;
  for (int cl = 0; cl < ncg; cl++) {
    if (cl + 1 < ncg) {
      int k0n = ((2 * (cl + 1) + wg) << 6);
      stage_chunk(gW[buf ^ 1], gR[buf ^ 1], W, ldw, u0, rhs, ldr, k0n, gtid);
      cp_wait<1>();
    } else {
      cp_wait<0>();
    }
    group_sync(wg);
#pragma unroll
    for (int kk = 0; kk < KC; kk += 4) {
      ulonglong2 w0 = *(const ulonglong2*)&gW[buf][r0][kk];
      ulonglong2 w1 = *(const ulonglong2*)&gW[buf][r1][kk];
#pragma unroll
      for (int j = 0; j < 4; j++) {
        ulonglong2 xv = *(const ulonglong2*)&gR[buf][bi + 8 * j][kk];
        ffma2(acc[0][j], w0.x, xv.x);
        ffma2(acc[0][j], w0.y, xv.y);
        ffma2(acc[1][j], w1.x, xv.x);
        ffma2(acc[1][j], w1.y, xv.y);
      }
    }
    group_sync(wg);
    buf ^= 1;
  }
}

// ------------- LSTM cell + zoneout for one (unit, batch) --------------------
__device__ __forceinline__ void cell_update(const float* sGp, const float* sB,
                                            int jj, int b, float uhv, float ucv,
                                            float& h_reg, float& c_reg,
                                            float& h_new_out) {
  // gates = partial(group0) + partial(group1) + bias
  const float* g0 = sGp;                  // sGp[0][row][col]
  const float* g1 = sGp + 32 * 33;        // sGp[1][row][col]
  float gi = g0[(jj)*33 + b]      + g1[(jj)*33 + b]      + sB[jj];
  float gf = g0[(8 + jj)*33 + b]  + g1[(8 + jj)*33 + b]  + sB[8 + jj];
  float gg = g0[(16 + jj)*33 + b] + g1[(16 + jj)*33 + b] + sB[16 + jj];
  float go = g0[(24 + jj)*33 + b] + g1[(24 + jj)*33 + b] + sB[24 + jj];
  float iv = sigmoidf_(gi);
  float fv = sigmoidf_(gf);
  float gv = tanhf(gg);
  float ov = sigmoidf_(go);
  float c_new = fv * c_reg + iv * gv;
  float h_new = ov * tanhf(c_new);
  h_new_out = h_new;
  c_reg = (ucv < 0.9f) ? c_new : c_reg;  // zoneout keep-mask
  h_reg = (uhv < 0.9f) ? h_new : h_reg;
}

// ---------------- init: reset barrier, zero parity-1 initial state ----------
__global__ void lstm_init_kernel() {
  unsigned i = blockIdx.x * blockDim.x + threadIdx.x;
  if (i == 0) g_bar = 0u;
  if (i < BB * HH) {
    g_h_state[1][0][i] = 0.0f;
    g_h_state[1][1][i] = 0.0f;
  }
}

// ---------------- main persistent kernel ------------------------------------
__global__ void __launch_bounds__(NTHR, 1)
lstm_main_kernel(const float* __restrict__ x,
                 const float* __restrict__ Wih0, const float* __restrict__ Whh0,
                 const float* __restrict__ bih0, const float* __restrict__ bhh0,
                 const float* __restrict__ Wih1, const float* __restrict__ Whh1,
                 const float* __restrict__ bih1, const float* __restrict__ bhh1,
                 const float* __restrict__ u_h, const float* __restrict__ u_c,
                 float* __restrict__ out) {
  extern __shared__ __align__(16) float dsm[];
  float (*sW)[2][32][SRS] = (float (*)[2][32][SRS])(dsm + SM_W);
  float (*sR)[2][32][SRS] = (float (*)[2][32][SRS])(dsm + SM_R);
  float* sGp = dsm + SM_G;                  // [2][32][33]
  float* sB = dsm + SM_B;                   // [2][32]

  const int tid = threadIdx.x;
  const int wg = tid >> 7;                  // warp-group 0/1 (K-parity)
  const int gtid = tid & (GTHR - 1);        // id within group
  const int u0 = blockIdx.x * 8;            // first hidden unit owned by CTA
  const int r0 = (gtid >> 3) * 2;           // gemm thread tile rows
  const int r1 = r0 + 1;
  const int bi = gtid & 7;                  // batches bi, bi+8, bi+16, bi+24
  const int jj = tid >> 5;                  // cell: unit index 0..7
  const int cb = tid & 31;                  // cell: batch index

  float (*gW)[32][SRS] = sW[wg];
  float (*gR)[32][SRS] = sR[wg];
  float* myGp = sGp + wg * 32 * 33;

  if (tid < 32) {
    int grow = (tid >> 3) * HH + u0 + (tid & 7);
    sB[0 * 32 + tid] = bih0[grow] + bhh0[grow];
    sB[1 * 32 + tid] = bih1[grow] + bhh1[grow];
  }
  __syncthreads();

  float h_reg[2] = {0.f, 0.f};
  float c_reg[2] = {0.f, 0.f};
  unsigned target = 0;

  for (int phase = 0; phase <= TT; phase++) {
    // ======== Layer 1 for step t = phase-1 ========
    if (phase >= 1) {
      const int t = phase - 1;
      unsigned long long acc[2][4] = {};
      sub_gemm(acc, Wih1, HH, u0, g_h0new[t & 1], HH, HH, wg, gtid, r0, r1, bi,
               gW, gR);
      sub_gemm(acc, Whh1, HH, u0, g_h_state[(t + 1) & 1][1], HH, HH, wg, gtid,
               r0, r1, bi, gW, gR);
#pragma unroll
      for (int j = 0; j < 4; j++) {
        myGp[r0 * 33 + bi + 8 * j] = pairsum(acc[0][j]);
        myGp[r1 * 33 + bi + 8 * j] = pairsum(acc[1][j]);
      }
      __syncthreads();
      {
        int hg = u0 + jj;
        size_t uoff = (((size_t)t * 2 + 1) * BB + cb) * HH + hg;
        float hn;
        cell_update(sGp, sB + 32, jj, cb, __ldcs(&u_h[uoff]), __ldcs(&u_c[uoff]),
                    h_reg[1], c_reg[1], hn);
        out[((size_t)t * BB + cb) * HH + hg] = hn;           // pre-zoneout
        g_h_state[t & 1][1][cb * HH + hg] = h_reg[1];        // post-zoneout
      }
      __syncthreads();
    }
    // ======== Layer 0 for step t = phase ========
    if (phase <= TT - 1) {
      const int t = phase;
      unsigned long long acc[2][4] = {};
      sub_gemm(acc, Wih0, DD, u0, x + (size_t)t * BB * DD, DD, DD, wg, gtid, r0,
               r1, bi, gW, gR);
      sub_gemm(acc, Whh0, HH, u0, g_h_state[(t + 1) & 1][0], HH, HH, wg, gtid,
               r0, r1, bi, gW, gR);
#pragma unroll
      for (int j = 0; j < 4; j++) {
        myGp[r0 * 33 + bi + 8 * j] = pairsum(acc[0][j]);
        myGp[r1 * 33 + bi + 8 * j] = pairsum(acc[1][j]);
      }
      __syncthreads();
      {
        int hg = u0 + jj;
        size_t uoff = (((size_t)t * 2 + 0) * BB + cb) * HH + hg;
        float hn;
        cell_update(sGp, sB, jj, cb, __ldcs(&u_h[uoff]), __ldcs(&u_c[uoff]),
                    h_reg[0], c_reg[0], hn);
        g_h0new[t & 1][cb * HH + hg] = hn;                   // pre-zoneout
        g_h_state[t & 1][0][cb * HH + hg] = h_reg[0];        // post-zoneout
      }
      target += NCTA;
      grid_sync(target);   // the ONE barrier per step
    }
  }

  // final carries: h_n (L,B,H) then c_n (L,B,H), after outputs (T,B,H)
  float* hn_out = out + (size_t)TT * BB * HH;
  float* cn_out = hn_out + (size_t)2 * BB * HH;
#pragma unroll
  for (int l = 0; l < 2; l++) {
    int hg = u0 + jj;
    hn_out[((size_t)l * BB + cb) * HH + hg] = h_reg[l];
    cn_out[((size_t)l * BB + cb) * HH + hg] = c_reg[l];
  }
}

extern "C" void kernel_launch(void* const* d_in, const int* in_sizes, int n_in,
                              void* d_out, int out_size) {
  const float* x    = (const float*)d_in[0];
  const float* Wih0 = (const float*)d_in[1];
  const float* Whh0 = (const float*)d_in[2];
  const float* bih0 = (const float*)d_in[3];
  const float* bhh0 = (const float*)d_in[4];
  const float* Wih1 = (const float*)d_in[5];
  const float* Whh1 = (const float*)d_in[6];
  const float* bih1 = (const float*)d_in[7];
  const float* bhh1 = (const float*)d_in[8];
  const float* u_h  = (const float*)d_in[9];
  const float* u_c  = (const float*)d_in[10];
  float* out = (float*)d_out;

  cudaFuncSetAttribute(lstm_main_kernel,
                       cudaFuncAttributeMaxDynamicSharedMemorySize,
                       SM_TOT_BYTES);

  lstm_init_kernel<<<(BB * HH + 255) / 256, 256>>>();
  lstm_main_kernel<<<NCTA, NTHR, SM_TOT_BYTES>>>(x, Wih0, Whh0, bih0, bhh0,
                                                 Wih1, Whh1, bih1, bhh1, u_h,
                                                 u_c, out);
}